// round 4
// baseline (speedup 1.0000x reference)
#include <cuda_runtime.h>

// BatchSecondOrderLPCSynth: B=32, T=131072, HOP=128, WIN=512, PAD=192, S=11 biquads.
// F = 1024 frames per batch row. Output (B, T) float32.
//
// Plan:
//   K1 (lpc_kernel): one thread per (b, f) frame. Software-pipelined 11-stage
//       all-pole cascade (stage s handles sample t = k - s at iteration k), so
//       the 22 FMAs per iteration are 11 independent 2-FMA chains (ILP hides
//       latency at low occupancy). Applies Hann window, writes the 512-sample
//       windowed frame to a 64MB __device__ scratch with float4 stores.
//   K2 (ola_kernel): per output sample, gathers the <=4 overlapping frame
//       contributions (coalesced) and divides by the window-norm computed from
//       the same validity mask the reference uses.

#define BB   32
#define TT   131072
#define FF   1024
#define HOP  128
#define WIN  512
#define PADD 192
#define NS   11

// 32 * 1024 * 512 floats = 64 MiB scratch for windowed frames.
__device__ float g_frames[BB * FF * WIN];

__global__ void __launch_bounds__(128) lpc_kernel(const float* __restrict__ ex,
                                                  const float* __restrict__ gain,
                                                  const float* __restrict__ biq) {
    __shared__ float win[WIN];
    for (int i = threadIdx.x; i < WIN; i += blockDim.x)
        win[i] = 0.5f - 0.5f * cospif((float)i * (1.0f / 256.0f));
    __syncthreads();

    const int fid = blockIdx.x * blockDim.x + threadIdx.x;   // 0 .. 32767
    const int b = fid >> 10;
    const int f = fid & (FF - 1);

    const float* exrow = ex + (size_t)b * TT;

    // Coefficients. y = (x - a1*y1 - a2*y2)/a0. Fold all 1/a0 into a single
    // front gain (cascade is linear; a0 == 1 in this dataset so the fold is
    // exact), leaving 2 FMAs per stage in the inner loop.
    float c1[NS], c2[NS], y1[NS], y2[NS];
    float gtot = gain[fid];
    {
        const float* bq = biq + (size_t)fid * (NS * 3);
        #pragma unroll
        for (int s = 0; s < NS; s++) {
            float inv = 1.0f / bq[3 * s + 0];
            c1[s] = -bq[3 * s + 1] * inv;
            c2[s] = -bq[3 * s + 2] * inv;
            gtot *= inv;
            y1[s] = 0.0f;
            y2[s] = 0.0f;
        }
    }

    float* frow = g_frames + (size_t)fid * WIN;
    const int base = f * HOP - PADD;     // ex index of frame sample k is base + k

    // Output staging registers for float4 stores.
    // Sample t is produced at iteration k = t + (NS - 1) = t + 10, so within a
    // k4 block (k4 % 4 == 0): t & 3 == (j + 2) & 3. The quad [k4-12, k4-9]
    // completes at j == 1.
    float o0 = 0.f, o1 = 0.f, o2 = 0.f, o3 = 0.f;

    for (int k4 = 0; k4 <= 520; k4 += 4) {
        float xin[4];
        if (k4 < 512) {
            int q0 = base + k4;                       // aligned: base%4==0, k4%4==0
            if (q0 >= 0 && q0 + 3 < TT) {
                float4 v = *reinterpret_cast<const float4*>(exrow + q0);
                xin[0] = v.x; xin[1] = v.y; xin[2] = v.z; xin[3] = v.w;
            } else {
                #pragma unroll
                for (int j = 0; j < 4; j++) {
                    int q = q0 + j;
                    xin[j] = (q >= 0 && q < TT) ? exrow[q] : 0.0f;
                }
            }
        } else {
            xin[0] = xin[1] = xin[2] = xin[3] = 0.0f;
        }

        #pragma unroll
        for (int j = 0; j < 4; j++) {
            // Pipelined cascade: stage s consumes stage s-1's output from the
            // PREVIOUS iteration (iterate s downward so y1[s-1] is still old).
            // 11 independent 2-FMA chains per iteration -> ILP ~22.
            #pragma unroll
            for (int s = NS - 1; s >= 1; s--) {
                float y = fmaf(c1[s], y1[s], y1[s - 1]);
                y = fmaf(c2[s], y2[s], y);
                y2[s] = y1[s];
                y1[s] = y;
            }
            {
                float y = fmaf(c1[0], y1[0], gtot * xin[j]);
                y = fmaf(c2[0], y2[0], y);
                y2[0] = y1[0];
                y1[0] = y;
            }

            // Stage 10's fresh output corresponds to sample t = k - 10.
            int t = k4 + j - 10;
            float val = y1[NS - 1] * win[t & (WIN - 1)];   // dead for t<0 / t>511

            if (j == 2)      o0 = val;                     // t & 3 == 0
            else if (j == 3) o1 = val;                     // t & 3 == 1
            else if (j == 0) o2 = val;                     // t & 3 == 2
            else {                                         // j == 1: quad complete
                o3 = val;
                if (k4 >= 12) {
                    float4 q;
                    q.x = o0; q.y = o1; q.z = o2; q.w = o3;
                    *reinterpret_cast<float4*>(frow + (k4 - 12)) = q;
                }
            }
        }
    }
}

__global__ void __launch_bounds__(256) ola_kernel(float* __restrict__ out) {
    __shared__ float win[WIN];
    for (int i = threadIdx.x; i < WIN; i += blockDim.x)
        win[i] = 0.5f - 0.5f * cospif((float)i * (1.0f / 256.0f));
    __syncthreads();

    int o = blockIdx.x * blockDim.x + threadIdx.x;         // 0 .. B*T-1 (exact grid)
    int b = o >> 17;                                       // T = 2^17
    int p = (o & (TT - 1)) + PADD;                         // padded-domain position
    int g = p >> 7;                                        // p / HOP
    int r = p & (HOP - 1);

    const float* fb = g_frames + (size_t)b * (FF * WIN);
    float acc = 0.0f, nrm = 0.0f;
    #pragma unroll
    for (int j = 0; j < 4; j++) {
        int fr = g - j;
        if (fr >= 0 && fr < FF) {
            int w = r + j * HOP;
            acc += fb[fr * WIN + w];
            nrm += win[w];
        }
    }
    out[o] = acc / nrm;
}

extern "C" void kernel_launch(void* const* d_in, const int* in_sizes, int n_in,
                              void* d_out, int out_size) {
    const float* ex   = (const float*)d_in[0];   // (32, 131072)
    const float* gain = (const float*)d_in[1];   // (32, 1024)
    const float* biq  = (const float*)d_in[2];   // (32, 1024, 11, 3)
    float* out = (float*)d_out;                  // (32, 131072)

    (void)in_sizes; (void)n_in; (void)out_size;

    lpc_kernel<<<(BB * FF) / 128, 128>>>(ex, gain, biq);
    ola_kernel<<<(BB * TT) / 256, 256>>>(out);
}

// round 5
// speedup vs baseline: 1.7558x; 1.7558x over previous
#include <cuda_runtime.h>

// BatchSecondOrderLPCSynth: B=32, T=131072, HOP=128, WIN=512, PAD=192, S=11 biquads.
// F = 1024 frames per batch row. Output (B, T) float32.
//
// R4 changes (from ncu on the 123us baseline):
//   K1: prefetch excitation quad one iteration ahead (hide LDG latency at low
//       occupancy), warp-uniform interior fast path, 32-thread CTAs for wave
//       balance (1024 CTAs over 148 SMs instead of 256).
//   K2: was issue-bound (issue=83%, alu=49%, DRAM=21%). Now 4 outputs per
//       thread: quad shares frame index g and validity mask (4 | HOP), so the
//       gather is 4 float4 LDGs + 4 float4 smem window reads + 1 STG.128.

#define BB   32
#define TT   131072
#define FF   1024
#define HOP  128
#define WIN  512
#define PADD 192
#define NS   11

// 32 * 1024 * 512 floats = 64 MiB scratch for windowed frames.
__device__ float g_frames[BB * FF * WIN];

__global__ void __launch_bounds__(32) lpc_kernel(const float* __restrict__ ex,
                                                 const float* __restrict__ gain,
                                                 const float* __restrict__ biq) {
    __shared__ float win[WIN];
    for (int i = threadIdx.x; i < WIN; i += blockDim.x)
        win[i] = 0.5f - 0.5f * cospif((float)i * (1.0f / 256.0f));
    __syncthreads();

    const int fid = blockIdx.x * blockDim.x + threadIdx.x;   // 0 .. 32767
    const int b = fid >> 10;
    const int f = fid & (FF - 1);

    const float* exrow = ex + (size_t)b * TT;

    // Coefficients. y = (x - a1*y1 - a2*y2)/a0. Fold all 1/a0 into a single
    // front gain (cascade is linear; a0 == 1 in this dataset so the fold is
    // exact), leaving 2 FMAs per stage in the inner loop.
    float c1[NS], c2[NS], y1[NS], y2[NS];
    float gtot = gain[fid];
    {
        const float* bq = biq + (size_t)fid * (NS * 3);
        #pragma unroll
        for (int s = 0; s < NS; s++) {
            float inv = 1.0f / bq[3 * s + 0];
            c1[s] = -bq[3 * s + 1] * inv;
            c2[s] = -bq[3 * s + 2] * inv;
            gtot *= inv;
            y1[s] = 0.0f;
            y2[s] = 0.0f;
        }
    }

    float* frow = g_frames + (size_t)fid * WIN;
    const int base = f * HOP - PADD;     // ex index of frame sample k is base + k
    // Frames f in [2, 1021] never touch the zero padding: warp-uniform except
    // in the two boundary warps.
    const bool interior = (base >= 0) && (base + 511 < TT);

    auto load4 = [&](int k4) -> float4 {
        int q0 = base + k4;                              // 4-aligned
        if (interior) {
            return *reinterpret_cast<const float4*>(exrow + q0);
        }
        float4 v;
        v.x = (q0 + 0 >= 0 && q0 + 0 < TT) ? exrow[q0 + 0] : 0.0f;
        v.y = (q0 + 1 >= 0 && q0 + 1 < TT) ? exrow[q0 + 1] : 0.0f;
        v.z = (q0 + 2 >= 0 && q0 + 2 < TT) ? exrow[q0 + 2] : 0.0f;
        v.w = (q0 + 3 >= 0 && q0 + 3 < TT) ? exrow[q0 + 3] : 0.0f;
        return v;
    };

    // Output staging registers for float4 stores.
    // Sample t is produced at iteration k = t + (NS - 1) = t + 10, so within a
    // k4 block (k4 % 4 == 0): t & 3 == (j + 2) & 3. The quad [k4-12, k4-9]
    // completes at j == 1.
    float o0 = 0.f, o1 = 0.f, o2 = 0.f, o3 = 0.f;

    // Software prefetch: pre holds the quad for the CURRENT iteration; the
    // next quad's LDG is issued before the cascade so its latency overlaps
    // the ~88 FMAs of this iteration.
    float4 pre = load4(0);

    for (int k4 = 0; k4 <= 520; k4 += 4) {
        float4 cur = pre;
        pre = (k4 + 4 < 512) ? load4(k4 + 4) : make_float4(0.f, 0.f, 0.f, 0.f);

        float xin[4] = {cur.x, cur.y, cur.z, cur.w};

        #pragma unroll
        for (int j = 0; j < 4; j++) {
            // Pipelined cascade: stage s consumes stage s-1's output from the
            // PREVIOUS iteration (iterate s downward so y1[s-1] is still old).
            // 11 independent 2-FMA chains per iteration -> ILP ~22.
            #pragma unroll
            for (int s = NS - 1; s >= 1; s--) {
                float y = fmaf(c1[s], y1[s], y1[s - 1]);
                y = fmaf(c2[s], y2[s], y);
                y2[s] = y1[s];
                y1[s] = y;
            }
            {
                float y = fmaf(c1[0], y1[0], gtot * xin[j]);
                y = fmaf(c2[0], y2[0], y);
                y2[0] = y1[0];
                y1[0] = y;
            }

            // Stage 10's fresh output corresponds to sample t = k - 10.
            int t = k4 + j - 10;
            float val = y1[NS - 1] * win[t & (WIN - 1)];   // dead for t<0 / t>511

            if (j == 2)      o0 = val;                     // t & 3 == 0
            else if (j == 3) o1 = val;                     // t & 3 == 1
            else if (j == 0) o2 = val;                     // t & 3 == 2
            else {                                         // j == 1: quad complete
                o3 = val;
                if (k4 >= 12) {
                    float4 q;
                    q.x = o0; q.y = o1; q.z = o2; q.w = o3;
                    *reinterpret_cast<float4*>(frow + (k4 - 12)) = q;
                }
            }
        }
    }
}

// 4 outputs per thread. o4 is 4-aligned and 4 | HOP, so all 4 samples of the
// quad share the same frame index g, residue block, and validity mask.
__global__ void __launch_bounds__(256) ola_kernel(float* __restrict__ out) {
    __shared__ float win[WIN];
    for (int i = threadIdx.x; i < WIN; i += blockDim.x)
        win[i] = 0.5f - 0.5f * cospif((float)i * (1.0f / 256.0f));
    __syncthreads();

    int idx = blockIdx.x * blockDim.x + threadIdx.x;       // 0 .. B*T/4-1
    int o4 = idx << 2;
    int b = o4 >> 17;                                      // T = 2^17
    int p = (o4 & (TT - 1)) + PADD;                        // padded-domain position
    int g = p >> 7;                                        // p / HOP
    int r = p & (HOP - 1);                                 // r % 4 == 0, r <= 124

    const float* fb = g_frames + (size_t)b * (FF * WIN);
    float ax = 0.f, ay = 0.f, az = 0.f, aw = 0.f;
    float nx = 0.f, ny = 0.f, nz = 0.f, nw = 0.f;

    #pragma unroll
    for (int j = 0; j < 4; j++) {
        int fr = g - j;
        if (fr >= 0 && fr < FF) {
            int w = r + j * HOP;                           // w+3 <= 511
            float4 v  = *reinterpret_cast<const float4*>(fb + fr * WIN + w);
            float4 wv = *reinterpret_cast<const float4*>(win + w);
            ax += v.x;  ay += v.y;  az += v.z;  aw += v.w;
            nx += wv.x; ny += wv.y; nz += wv.z; nw += wv.w;
        }
    }

    float4 res;
    res.x = ax / nx;
    res.y = ay / ny;
    res.z = az / nz;
    res.w = aw / nw;
    *reinterpret_cast<float4*>(out + o4) = res;
}

extern "C" void kernel_launch(void* const* d_in, const int* in_sizes, int n_in,
                              void* d_out, int out_size) {
    const float* ex   = (const float*)d_in[0];   // (32, 131072)
    const float* gain = (const float*)d_in[1];   // (32, 1024)
    const float* biq  = (const float*)d_in[2];   // (32, 1024, 11, 3)
    float* out = (float*)d_out;                  // (32, 131072)

    (void)in_sizes; (void)n_in; (void)out_size;

    lpc_kernel<<<(BB * FF) / 32, 32>>>(ex, gain, biq);
    ola_kernel<<<(BB * TT) / (4 * 256), 256>>>(out);
}

// round 15
// speedup vs baseline: 1.8250x; 1.0394x over previous
#include <cuda_runtime.h>

// BatchSecondOrderLPCSynth: B=32, T=131072, HOP=128, WIN=512, PAD=192, S=11 biquads.
// F = 1024 frames per batch row. Output (B, T) float32.
//
// R6 changes:
//   K1: windowing REMOVED from the serial kernel (it was an LDS with 29-cyc
//       latency issued+consumed per sample -- the dominant stall). K1 now
//       stores raw cascade output; inner loop is pure register FMA chains +
//       one prefetched LDG.128 + one STG.128 per 4 samples.
//   K2: applies the Hann window during the gather (it already loads win[w]
//       for the norm), and processes 8 outputs/thread (8 | HOP so the quad
//       shares frame index + validity mask) to cut issue overhead.

#define BB   32
#define TT   131072
#define FF   1024
#define HOP  128
#define WIN  512
#define PADD 192
#define NS   11

// 32 * 1024 * 512 floats = 64 MiB scratch for (unwindowed) frame outputs.
__device__ float g_frames[BB * FF * WIN];

__global__ void __launch_bounds__(32) lpc_kernel(const float* __restrict__ ex,
                                                 const float* __restrict__ gain,
                                                 const float* __restrict__ biq) {
    const int fid = blockIdx.x * blockDim.x + threadIdx.x;   // 0 .. 32767
    const int b = fid >> 10;
    const int f = fid & (FF - 1);

    const float* exrow = ex + (size_t)b * TT;

    // Coefficients. y = (x - a1*y1 - a2*y2)/a0. Fold all 1/a0 into a single
    // front gain (cascade is linear; a0 == 1 in this dataset so the fold is
    // exact), leaving 2 FMAs per stage in the inner loop.
    float c1[NS], c2[NS], y1[NS], y2[NS];
    float gtot = gain[fid];
    {
        const float* bq = biq + (size_t)fid * (NS * 3);
        #pragma unroll
        for (int s = 0; s < NS; s++) {
            float inv = 1.0f / bq[3 * s + 0];
            c1[s] = -bq[3 * s + 1] * inv;
            c2[s] = -bq[3 * s + 2] * inv;
            gtot *= inv;
            y1[s] = 0.0f;
            y2[s] = 0.0f;
        }
    }

    float* frow = g_frames + (size_t)fid * WIN;
    const int base = f * HOP - PADD;     // ex index of frame sample k is base + k
    // Frames f in [2, 1021] never touch the zero padding: warp-uniform except
    // in the two boundary warps.
    const bool interior = (base >= 0) && (base + 511 < TT);

    auto load4 = [&](int k4) -> float4 {
        int q0 = base + k4;                              // 4-aligned
        if (interior) {
            return *reinterpret_cast<const float4*>(exrow + q0);
        }
        float4 v;
        v.x = (q0 + 0 >= 0 && q0 + 0 < TT) ? exrow[q0 + 0] : 0.0f;
        v.y = (q0 + 1 >= 0 && q0 + 1 < TT) ? exrow[q0 + 1] : 0.0f;
        v.z = (q0 + 2 >= 0 && q0 + 2 < TT) ? exrow[q0 + 2] : 0.0f;
        v.w = (q0 + 3 >= 0 && q0 + 3 < TT) ? exrow[q0 + 3] : 0.0f;
        return v;
    };

    // Output staging registers for float4 stores.
    // Sample t is produced at iteration k = t + (NS - 1) = t + 10, so within a
    // k4 block (k4 % 4 == 0): t & 3 == (j + 2) & 3. The quad [k4-12, k4-9]
    // completes at j == 1.
    float o0 = 0.f, o1 = 0.f, o2 = 0.f, o3 = 0.f;

    // Software prefetch: pre holds the quad for the CURRENT iteration; the
    // next quad's LDG is issued before the cascade so its latency overlaps
    // the ~88 FMAs of this iteration.
    float4 pre = load4(0);

    for (int k4 = 0; k4 <= 520; k4 += 4) {
        float4 cur = pre;
        pre = (k4 + 4 < 512) ? load4(k4 + 4) : make_float4(0.f, 0.f, 0.f, 0.f);

        float xin[4] = {cur.x, cur.y, cur.z, cur.w};

        #pragma unroll
        for (int j = 0; j < 4; j++) {
            // Pipelined cascade: stage s consumes stage s-1's output from the
            // PREVIOUS iteration (iterate s downward so y1[s-1] is still old).
            // 11 independent 2-FMA chains per iteration -> ILP ~22.
            #pragma unroll
            for (int s = NS - 1; s >= 1; s--) {
                float y = fmaf(c1[s], y1[s], y1[s - 1]);
                y = fmaf(c2[s], y2[s], y);
                y2[s] = y1[s];
                y1[s] = y;
            }
            {
                float y = fmaf(c1[0], y1[0], gtot * xin[j]);
                y = fmaf(c2[0], y2[0], y);
                y2[0] = y1[0];
                y1[0] = y;
            }

            // Stage 10's fresh output is sample t = k - 10 (unwindowed; the
            // Hann window is applied in ola_kernel).
            float val = y1[NS - 1];

            if (j == 2)      o0 = val;                     // t & 3 == 0
            else if (j == 3) o1 = val;                     // t & 3 == 1
            else if (j == 0) o2 = val;                     // t & 3 == 2
            else {                                         // j == 1: quad complete
                o3 = val;
                if (k4 >= 12) {
                    float4 q;
                    q.x = o0; q.y = o1; q.z = o2; q.w = o3;
                    *reinterpret_cast<float4*>(frow + (k4 - 12)) = q;
                }
            }
        }
    }
}

// 8 outputs per thread. o8 is 8-aligned and 8 | HOP, so all 8 samples of the
// quad-pair share the same frame index g, residue block, and validity mask.
// Applies the Hann window here (same y*win product/rounding as the reference).
__global__ void __launch_bounds__(256) ola_kernel(float* __restrict__ out) {
    __shared__ float win[WIN];
    for (int i = threadIdx.x; i < WIN; i += blockDim.x)
        win[i] = 0.5f - 0.5f * cospif((float)i * (1.0f / 256.0f));
    __syncthreads();

    int idx = blockIdx.x * blockDim.x + threadIdx.x;       // 0 .. B*T/8-1
    int o8 = idx << 3;
    int b = o8 >> 17;                                      // T = 2^17
    int p = (o8 & (TT - 1)) + PADD;                        // padded-domain position
    int g = p >> 7;                                        // p / HOP
    int r = p & (HOP - 1);                                 // r % 8 == 0, r <= 120

    const float* fb = g_frames + (size_t)b * (FF * WIN);
    float acc[8] = {0.f, 0.f, 0.f, 0.f, 0.f, 0.f, 0.f, 0.f};
    float nrm[8] = {0.f, 0.f, 0.f, 0.f, 0.f, 0.f, 0.f, 0.f};

    #pragma unroll
    for (int j = 0; j < 4; j++) {
        int fr = g - j;
        if (fr >= 0 && fr < FF) {
            int w = r + j * HOP;                           // w+7 <= 511
            const float* src = fb + fr * WIN + w;
            float4 v0  = *reinterpret_cast<const float4*>(src);
            float4 v1  = *reinterpret_cast<const float4*>(src + 4);
            float4 wv0 = *reinterpret_cast<const float4*>(win + w);
            float4 wv1 = *reinterpret_cast<const float4*>(win + w + 4);
            acc[0] = fmaf(v0.x, wv0.x, acc[0]); nrm[0] += wv0.x;
            acc[1] = fmaf(v0.y, wv0.y, acc[1]); nrm[1] += wv0.y;
            acc[2] = fmaf(v0.z, wv0.z, acc[2]); nrm[2] += wv0.z;
            acc[3] = fmaf(v0.w, wv0.w, acc[3]); nrm[3] += wv0.w;
            acc[4] = fmaf(v1.x, wv1.x, acc[4]); nrm[4] += wv1.x;
            acc[5] = fmaf(v1.y, wv1.y, acc[5]); nrm[5] += wv1.y;
            acc[6] = fmaf(v1.z, wv1.z, acc[6]); nrm[6] += wv1.z;
            acc[7] = fmaf(v1.w, wv1.w, acc[7]); nrm[7] += wv1.w;
        }
    }

    float4 r0, r1;
    r0.x = acc[0] / nrm[0];
    r0.y = acc[1] / nrm[1];
    r0.z = acc[2] / nrm[2];
    r0.w = acc[3] / nrm[3];
    r1.x = acc[4] / nrm[4];
    r1.y = acc[5] / nrm[5];
    r1.z = acc[6] / nrm[6];
    r1.w = acc[7] / nrm[7];
    *reinterpret_cast<float4*>(out + o8)     = r0;
    *reinterpret_cast<float4*>(out + o8 + 4) = r1;
}

extern "C" void kernel_launch(void* const* d_in, const int* in_sizes, int n_in,
                              void* d_out, int out_size) {
    const float* ex   = (const float*)d_in[0];   // (32, 131072)
    const float* gain = (const float*)d_in[1];   // (32, 1024)
    const float* biq  = (const float*)d_in[2];   // (32, 1024, 11, 3)
    float* out = (float*)d_out;                  // (32, 131072)

    (void)in_sizes; (void)n_in; (void)out_size;

    lpc_kernel<<<(BB * FF) / 32, 32>>>(ex, gain, biq);
    ola_kernel<<<(BB * TT) / (8 * 256), 256>>>(out);
}